// round 11
// baseline (speedup 1.0000x reference)
#include <cuda_runtime.h>
#include <cuda_bf16.h>
#include <cuda_fp16.h>
#include <math.h>
#include <stdint.h>

// Problem constants (fixed shapes)
#define BB   8
#define CC   512
#define NN_  2048
#define RR   (BB * NN_)      // 16384 positions
#define MLPH 2048
#define KH   9
#define PAD  4

// ---------------- scratch (device globals; no allocs allowed) ----------------
__device__ __align__(16) float g_Qt [(size_t)RR * CC];   // raw query (residual)
__device__ __align__(16) float g_X  [(size_t)RR * CC];
__device__ __align__(16) float g_H2 [(size_t)RR * CC];
__device__ __align__(16) float4 g_stats[RR];             // qm,qrs,km,krs

// fp16 activations
__device__ __align__(16) __half g_Qa [(size_t)RR * CC];
__device__ __align__(16) __half g_Ka [(size_t)RR * CC];
__device__ __align__(16) __half g_Va [(size_t)RR * CC];
__device__ __align__(16) __half g_Qpa[(size_t)RR * CC];   // projected Q (fp16)
__device__ __align__(16) __half g_Kpa[(size_t)RR * CC];
__device__ __align__(16) __half g_Vpa[(size_t)RR * CC];
__device__ __align__(16) __half g_L2a[(size_t)RR * CC];
__device__ __align__(16) __half g_Ha [(size_t)RR * MLPH];

// fp16 weights
__device__ __align__(16) __half g_wq[CC * CC];
__device__ __align__(16) __half g_wk[CC * CC];
__device__ __align__(16) __half g_wv[CC * CC];
__device__ __align__(16) __half g_w1[MLPH * CC];  // w1^T
__device__ __align__(16) __half g_w2[CC * MLPH];  // w2^T

// ---------------- helpers ----------------------------------------------------
__device__ __forceinline__ uint32_t smem_u32(const void* p) {
    uint32_t a;
    asm("{ .reg .u64 t; cvta.to.shared.u64 t, %1; cvt.u32.u64 %0, t; }"
        : "=r"(a) : "l"(p));
    return a;
}
__device__ __forceinline__ void cpa16(uint32_t dst, const void* src) {
    asm volatile("cp.async.cg.shared.global [%0], [%1], 16;"
                 :: "r"(dst), "l"(src) : "memory");
}
#define CP_COMMIT() asm volatile("cp.async.commit_group;" ::: "memory")
#define CP_WAIT(n)  asm volatile("cp.async.wait_group %0;" :: "n"(n) : "memory")

__device__ __forceinline__ void ldsm4(uint32_t& r0, uint32_t& r1,
                                      uint32_t& r2, uint32_t& r3, uint32_t a) {
    asm volatile("ldmatrix.sync.aligned.m8n8.x4.shared.b16 {%0,%1,%2,%3}, [%4];"
                 : "=r"(r0), "=r"(r1), "=r"(r2), "=r"(r3) : "r"(a));
}
__device__ __forceinline__ void mma16816(float* c, uint32_t a0, uint32_t a1,
                                         uint32_t a2, uint32_t a3,
                                         uint32_t b0, uint32_t b1) {
    asm volatile(
        "mma.sync.aligned.m16n8k16.row.col.f32.f16.f16.f32 "
        "{%0,%1,%2,%3}, {%4,%5,%6,%7}, {%8,%9}, {%0,%1,%2,%3};"
        : "+f"(c[0]), "+f"(c[1]), "+f"(c[2]), "+f"(c[3])
        : "r"(a0), "r"(a1), "r"(a2), "r"(a3), "r"(b0), "r"(b1));
}
// smem layout: rows of 32 fp16 (64B); 16B units XOR-swizzled by (row>>1)&3
__device__ __forceinline__ uint32_t swoff(int row, int kb) {
    return (uint32_t)((row << 6) + ((((kb >> 4) ^ ((row >> 1) & 3))) << 4));
}

// ============================================================================
// K1a: per-position LN stats (coalesced along n)
// ============================================================================
__global__ __launch_bounds__(256) void k_stats(
    const float* __restrict__ q,  const float* __restrict__ k,
    const float* __restrict__ qe, const float* __restrict__ ke)
{
    int b  = blockIdx.y;
    int n0 = blockIdx.x * 32;
    int tx = threadIdx.x & 31;
    int ty = threadIdx.x >> 5;     // 0..7
    size_t base = (size_t)b * CC * NN_ + n0 + tx;

    float qs = 0.f, qss = 0.f, ks = 0.f, kss = 0.f;
    for (int c = ty; c < CC; c += 8) {
        size_t idx = base + (size_t)c * NN_;
        float qv = q[idx] + qe[idx];
        float kv = k[idx] + ke[idx];
        qs += qv; qss += qv * qv;
        ks += kv; kss += kv * kv;
    }
    __shared__ float sm[4][8][32];
    sm[0][ty][tx] = qs; sm[1][ty][tx] = qss;
    sm[2][ty][tx] = ks; sm[3][ty][tx] = kss;
    __syncthreads();
    if (ty == 0) {
        float a0 = 0.f, a1 = 0.f, a2 = 0.f, a3 = 0.f;
#pragma unroll
        for (int w = 0; w < 8; w++) {
            a0 += sm[0][w][tx]; a1 += sm[1][w][tx];
            a2 += sm[2][w][tx]; a3 += sm[3][w][tx];
        }
        const float invC = 1.0f / CC;
        float qm = a0 * invC, km = a2 * invC;
        float qrs = rsqrtf(a1 * invC - qm * qm + 1e-5f);
        float krs = rsqrtf(a3 * invC - km * km + 1e-5f);
        g_stats[b * NN_ + n0 + tx] = make_float4(qm, qrs, km, krs);
    }
}

// ============================================================================
// K1b: transpose-convert: apply LN, emit pos-major fp16 (+ raw q fp32)
// ============================================================================
__global__ __launch_bounds__(256) void k_cvtT(
    const float* __restrict__ q,  const float* __restrict__ k,
    const float* __restrict__ qe, const float* __restrict__ ke,
    const float* __restrict__ gn, const float* __restrict__ bn)
{
    __shared__ float tQE[32][33], tKE[32][33], tQ[32][33], tK[32][33];
    int b  = blockIdx.z;
    int c0 = blockIdx.y * 32;
    int n0 = blockIdx.x * 32;
    int tx = threadIdx.x;      // 0..31
    int ty = threadIdx.y;      // 0..7

#pragma unroll
    for (int i = 0; i < 4; i++) {
        int cl = ty + i * 8;
        size_t idx = (size_t)b * CC * NN_ + (size_t)(c0 + cl) * NN_ + n0 + tx;
        float qv = q[idx], kv = k[idx];
        tQ [cl][tx] = qv;
        tK [cl][tx] = kv;
        tQE[cl][tx] = qv + qe[idx];
        tKE[cl][tx] = kv + ke[idx];
    }
    __syncthreads();

    int c = c0 + tx;
    float g = gn[c], bb = bn[c];
#pragma unroll
    for (int i = 0; i < 4; i++) {
        int nl = ty + i * 8;
        int r  = b * NN_ + n0 + nl;
        float4 s = g_stats[r];
        float qo = (tQE[tx][nl] - s.x) * s.y * g + bb;
        float ko = (tKE[tx][nl] - s.z) * s.w * g + bb;
        size_t o = (size_t)r * CC + c;
        g_Qa[o] = __float2half_rn(qo);
        g_Ka[o] = __float2half_rn(ko);
        g_Va[o] = __float2half_rn(tK[tx][nl]);
        g_Qt[o] = tQ[tx][nl];
    }
}

// ============================================================================
// plain fp16 mma.sync GEMM:  C[M,Nd] = A[M,K] * B[Nd,K]^T (+bias)
// 128x128x32 CTA tile, 8 warps (2x4), 3-stage cp.async, 2 CTAs/SM.
// OUT=0: fp32 store.  OUT=1: exact-GELU fp16 store.  OUT=2: fp16 store.
// ============================================================================
#define ST_BYTES 16384          // per stage: A 8K | B 8K
#define NSTAGE   3
#define GEMM_SMEM (NSTAGE * ST_BYTES)

__device__ __forceinline__ void ld_tile(uint32_t sdst,
                                        const __half* __restrict__ src,
                                        int ldk) {
    int tid = threadIdx.x;
#pragma unroll
    for (int it = 0; it < 2; it++) {
        int f   = tid + it * 256;   // 0..511
        int row = f >> 2;           // 0..127
        int u   = f & 3;            // 16B unit within 64B row
        uint32_t d = sdst + (uint32_t)(row << 6) + (uint32_t)(((u ^ ((row >> 1) & 3))) << 4);
        cpa16(d, src + (size_t)row * ldk + u * 8);
    }
}

__device__ __forceinline__ void ld_stage(
    uint32_t sbase,
    const __half* __restrict__ A, const __half* __restrict__ B,
    int brow, int bcol, int K, int k0)
{
    ld_tile(sbase +    0, A + (size_t)brow * K + k0, K);
    ld_tile(sbase + 8192, B + (size_t)bcol * K + k0, K);
}

template <int OUT>
__device__ __forceinline__ void gemm_body(
    const __half* __restrict__ A, const __half* __restrict__ B,
    const float* __restrict__ bias,
    float* __restrict__ Cf, __half* __restrict__ Ch,
    int Nd, int K, int brow, int bcol, char* smem)
{
    uint32_t sb = smem_u32(smem);
    const int tid  = threadIdx.x;
    const int lane = tid & 31;
    const int wid  = tid >> 5;
    const int wr   = wid >> 2;          // 0..1 (64 m rows)
    const int wc   = wid & 3;           // 0..3 (32 n cols)

    float acc[4][4][4];
#pragma unroll
    for (int i = 0; i < 4; i++)
#pragma unroll
        for (int j = 0; j < 4; j++)
#pragma unroll
            for (int x = 0; x < 4; x++) acc[i][j][x] = 0.f;

    const int a_row = wr * 64 + (lane & 15);
    const int a_kb  = (lane & 16);
    const int b_row = wc * 32 + (lane & 7) + ((lane & 16) ? 8 : 0);
    const int b_kb  = ((lane & 8) ? 16 : 0);

    const int NCH = K >> 5;

    // prologue: stages 0 and 1 in flight
    ld_stage(sb, A, B, brow, bcol, K, 0);
    CP_COMMIT();
    ld_stage(sb + ST_BYTES, A, B, brow, bcol, K, 32);
    CP_COMMIT();

    int s = 0;
    for (int ch = 0; ch < NCH; ch++) {
        if (ch + 2 < NCH) {
            int sn = s + 2; if (sn >= NSTAGE) sn -= NSTAGE;
            ld_stage(sb + (uint32_t)(sn * ST_BYTES), A, B,
                     brow, bcol, K, (ch + 2) << 5);
            CP_COMMIT();
            CP_WAIT(2);
        } else if (ch + 1 < NCH) {
            CP_WAIT(1);
        } else {
            CP_WAIT(0);
        }
        __syncthreads();

        uint32_t sa = sb + (uint32_t)(s * ST_BYTES);
#pragma unroll
        for (int ks = 0; ks < 2; ks++) {
            int kso = ks * 32;
            uint32_t bmat[4][2];
#pragma unroll
            for (int jp = 0; jp < 2; jp++) {
                uint32_t addr = sa + 8192 + swoff(b_row + jp * 16, b_kb + kso);
                ldsm4(bmat[2*jp][0], bmat[2*jp][1],
                      bmat[2*jp+1][0], bmat[2*jp+1][1], addr);
            }
#pragma unroll
            for (int i = 0; i < 4; i++) {
                uint32_t a0, a1, a2, a3;
                ldsm4(a0, a1, a2, a3, sa + swoff(a_row + i * 16, a_kb + kso));
#pragma unroll
                for (int j = 0; j < 4; j++)
                    mma16816(acc[i][j], a0, a1, a2, a3, bmat[j][0], bmat[j][1]);
            }
        }
        __syncthreads();
        s++; if (s >= NSTAGE) s = 0;
    }

    const int grp = lane >> 2, qr = lane & 3;
#pragma unroll
    for (int i = 0; i < 4; i++) {
        int r0 = brow + wr * 64 + i * 16 + grp;
#pragma unroll
        for (int j = 0; j < 4; j++) {
            int col = bcol + wc * 32 + j * 8 + qr * 2;
            float b0 = bias[col], b1 = bias[col + 1];
            float v00 = acc[i][j][0] + b0, v01 = acc[i][j][1] + b1;
            float v10 = acc[i][j][2] + b0, v11 = acc[i][j][3] + b1;
            if (OUT == 0) {
                *(float2*)(Cf + (size_t)r0 * Nd + col)       = make_float2(v00, v01);
                *(float2*)(Cf + (size_t)(r0 + 8) * Nd + col) = make_float2(v10, v11);
            } else if (OUT == 1) {
                v00 = 0.5f * v00 * (1.0f + erff(v00 * 0.70710678118654752f));
                v01 = 0.5f * v01 * (1.0f + erff(v01 * 0.70710678118654752f));
                v10 = 0.5f * v10 * (1.0f + erff(v10 * 0.70710678118654752f));
                v11 = 0.5f * v11 * (1.0f + erff(v11 * 0.70710678118654752f));
                *(__half2*)(Ch + (size_t)r0 * Nd + col)       = __floats2half2_rn(v00, v01);
                *(__half2*)(Ch + (size_t)(r0 + 8) * Nd + col) = __floats2half2_rn(v10, v11);
            } else {
                *(__half2*)(Ch + (size_t)r0 * Nd + col)       = __floats2half2_rn(v00, v01);
                *(__half2*)(Ch + (size_t)(r0 + 8) * Nd + col) = __floats2half2_rn(v10, v11);
            }
        }
    }
}

template <int OUT>
__global__ __launch_bounds__(256, 2) void mma_gemm(
    const __half* __restrict__ A, const __half* __restrict__ B,
    const float* __restrict__ bias,
    float* __restrict__ Cf, __half* __restrict__ Ch,
    int Nd, int K)
{
    extern __shared__ char smem[];
    gemm_body<OUT>(A, B, bias, Cf, Ch,
                   Nd, K, blockIdx.y * 128, blockIdx.x * 128, smem);
}

// merged projection GEMM: blockIdx.z selects (Q,K,V); fp16 outputs
__global__ __launch_bounds__(256, 2) void mma_gemm_proj(
    const __half* __restrict__ A0, const __half* __restrict__ A1,
    const __half* __restrict__ A2,
    const __half* __restrict__ B0, const __half* __restrict__ B1,
    const __half* __restrict__ B2,
    const float* __restrict__ b0, const float* __restrict__ b1,
    const float* __restrict__ b2,
    __half* __restrict__ C0, __half* __restrict__ C1, __half* __restrict__ C2)
{
    extern __shared__ char smem[];
    int z = blockIdx.z;
    const __half* Aa = (z == 0) ? A0 : (z == 1) ? A1 : A2;
    const __half* Bb = (z == 0) ? B0 : (z == 1) ? B1 : B2;
    const float* bs = (z == 0) ? b0 : (z == 1) ? b1 : b2;
    __half* Cc = (z == 0) ? C0 : (z == 1) ? C1 : C2;
    gemm_body<2>(Aa, Bb, bs, nullptr, Cc,
                 CC, CC, blockIdx.y * 128, blockIdx.x * 128, smem);
}

// ============================================================================
// K4: windowed attention + residual + LN2 (fp16 in, fp16 L2 out).
// ============================================================================
__global__ __launch_bounds__(256) void k_attn(
    const float* __restrict__ g2, const float* __restrict__ b2)
{
    int r  = blockIdx.x;
    int bb = r >> 11;
    int n  = r & (NN_ - 1);
    int tid = threadIdx.x;
    const float scale = 0.044194173824159216f;  // 512^-0.5

    bool   valid[KH];
    size_t nb[KH];
#pragma unroll
    for (int j = 0; j < KH; j++) {
        int nn = n + j - PAD;
        valid[j] = (nn >= 0) && (nn < NN_);
        nb[j] = valid[j] ? ((size_t)(bb * NN_ + nn)) * CC : 0;
    }

    size_t qb = (size_t)r * CC;
    float acc[KH];
#pragma unroll
    for (int j = 0; j < KH; j++) acc[j] = 0.f;

#pragma unroll
    for (int it = 0; it < 2; it++) {
        int c = tid + it * 256;
        float qv = __half2float(g_Qpa[qb + c]);
#pragma unroll
        for (int j = 0; j < KH; j++)
            if (valid[j]) acc[j] = fmaf(qv, __half2float(g_Kpa[nb[j] + c]), acc[j]);
    }

    __shared__ float sm[KH][8];
#pragma unroll
    for (int j = 0; j < KH; j++) {
#pragma unroll
        for (int o = 16; o > 0; o >>= 1)
            acc[j] += __shfl_down_sync(0xffffffffu, acc[j], o);
    }
    if ((tid & 31) == 0) {
        int w = tid >> 5;
#pragma unroll
        for (int j = 0; j < KH; j++) sm[j][w] = acc[j];
    }
    __syncthreads();
    __shared__ float wt[KH];
    if (tid < KH) {
        float s = 0.f;
#pragma unroll
        for (int w = 0; w < 8; w++) s += sm[tid][w];
        wt[tid] = s;
    }
    __syncthreads();

    float m = wt[0];
#pragma unroll
    for (int j = 1; j < KH; j++) m = fmaxf(m, wt[j]);
    float wj[KH], es = 0.f;
#pragma unroll
    for (int j = 0; j < KH; j++) { wj[j] = expf(wt[j] - m); es += wj[j]; }
    float inv = scale / es;
#pragma unroll
    for (int j = 0; j < KH; j++) wj[j] *= inv;

    float xv[2], xs = 0.f, xss = 0.f;
#pragma unroll
    for (int it = 0; it < 2; it++) {
        int c = tid + it * 256;
        float s = 0.f;
#pragma unroll
        for (int j = 0; j < KH; j++)
            if (valid[j]) s = fmaf(wj[j], __half2float(g_Vpa[nb[j] + c]), s);
        float x = g_Qt[qb + c] + s;
        g_X[qb + c] = x;
        xv[it] = x; xs += x; xss += x * x;
    }
    __syncthreads();
#pragma unroll
    for (int o = 16; o > 0; o >>= 1) {
        xs  += __shfl_down_sync(0xffffffffu, xs,  o);
        xss += __shfl_down_sync(0xffffffffu, xss, o);
    }
    if ((tid & 31) == 0) { int w = tid >> 5; sm[0][w] = xs; sm[1][w] = xss; }
    __syncthreads();
    float fs = 0.f, fss = 0.f;
#pragma unroll
    for (int w = 0; w < 8; w++) { fs += sm[0][w]; fss += sm[1][w]; }
    const float invC = 1.0f / CC;
    float mean = fs * invC;
    float rstd = rsqrtf(fss * invC - mean * mean + 1e-5f);
#pragma unroll
    for (int it = 0; it < 2; it++) {
        int c = tid + it * 256;
        float v = (xv[it] - mean) * rstd * g2[c] + b2[c];
        g_L2a[qb + c] = __float2half_rn(v);
    }
}

// ============================================================================
// weight prep
// ============================================================================
__global__ __launch_bounds__(256) void k_cvt(
    const float* __restrict__ src, __half* __restrict__ dst, int n)
{
    int i = blockIdx.x * 256 + threadIdx.x;
    if (i < n) dst[i] = __float2half_rn(src[i]);
}

// src [R, Cc] fp32 -> dst [Cc, R] fp16
__global__ void k_tcvt(const float* __restrict__ src,
                       __half* __restrict__ dst, int R, int Cc)
{
    __shared__ float t[32][33];
    int c0 = blockIdx.x * 32, r0 = blockIdx.y * 32;
    int tx = threadIdx.x, ty = threadIdx.y;
#pragma unroll
    for (int i = 0; i < 4; i++)
        t[ty + i * 8][tx] = src[(size_t)(r0 + ty + i * 8) * Cc + c0 + tx];
    __syncthreads();
#pragma unroll
    for (int i = 0; i < 4; i++) {
        float v = t[tx][ty + i * 8];
        dst[(size_t)(c0 + ty + i * 8) * R + r0 + tx] = __float2half_rn(v);
    }
}

// ============================================================================
// K7: out[b,c,n] = X[r,c] + H2[r,c]
// ============================================================================
__global__ __launch_bounds__(256) void k_out(float* __restrict__ out)
{
    __shared__ float t[32][33];
    int bb = blockIdx.z;
    int c0 = blockIdx.y * 32;
    int n0 = blockIdx.x * 32;
    int tx = threadIdx.x;
    int ty = threadIdx.y;
#pragma unroll
    for (int i = 0; i < 4; i++) {
        int n = n0 + ty + i * 8;
        size_t idx = ((size_t)(bb * NN_ + n)) * CC + c0 + tx;
        t[tx][ty + i * 8] = g_X[idx] + g_H2[idx];
    }
    __syncthreads();
#pragma unroll
    for (int i = 0; i < 4; i++) {
        int c = c0 + ty + i * 8;
        out[(size_t)bb * CC * NN_ + (size_t)c * NN_ + n0 + tx] = t[ty + i * 8][tx];
    }
}

// ============================================================================
extern "C" void kernel_launch(void* const* d_in, const int* in_sizes, int n_in,
                              void* d_out, int out_size)
{
    const float* query = (const float*)d_in[0];
    const float* key   = (const float*)d_in[1];
    const float* qe    = (const float*)d_in[2];
    const float* ke    = (const float*)d_in[3];
    const float* wq    = (const float*)d_in[4];
    const float* bq    = (const float*)d_in[5];
    const float* wk    = (const float*)d_in[6];
    const float* bk    = (const float*)d_in[7];
    const float* wv    = (const float*)d_in[8];
    const float* bv    = (const float*)d_in[9];
    const float* gn    = (const float*)d_in[10];
    const float* bn    = (const float*)d_in[11];
    const float* g2    = (const float*)d_in[12];
    const float* b2    = (const float*)d_in[13];
    const float* w1    = (const float*)d_in[14];
    const float* b1    = (const float*)d_in[15];
    const float* w2    = (const float*)d_in[16];
    const float* b2b   = (const float*)d_in[17];
    float* out = (float*)d_out;

    float* H2;
    __half *Qa, *Ka, *Va, *Qpa, *Kpa, *Vpa, *L2a, *Ha;
    __half *wqd, *wkd, *wvd, *w1d, *w2d;
    cudaGetSymbolAddress((void**)&H2,  g_H2);
    cudaGetSymbolAddress((void**)&Qa,  g_Qa);
    cudaGetSymbolAddress((void**)&Ka,  g_Ka);
    cudaGetSymbolAddress((void**)&Va,  g_Va);
    cudaGetSymbolAddress((void**)&Qpa, g_Qpa);
    cudaGetSymbolAddress((void**)&Kpa, g_Kpa);
    cudaGetSymbolAddress((void**)&Vpa, g_Vpa);
    cudaGetSymbolAddress((void**)&L2a, g_L2a);
    cudaGetSymbolAddress((void**)&Ha,  g_Ha);
    cudaGetSymbolAddress((void**)&wqd, g_wq);
    cudaGetSymbolAddress((void**)&wkd, g_wk);
    cudaGetSymbolAddress((void**)&wvd, g_wv);
    cudaGetSymbolAddress((void**)&w1d, g_w1);
    cudaGetSymbolAddress((void**)&w2d, g_w2);

    cudaFuncSetAttribute(mma_gemm<0>,  cudaFuncAttributeMaxDynamicSharedMemorySize, GEMM_SMEM);
    cudaFuncSetAttribute(mma_gemm<1>,  cudaFuncAttributeMaxDynamicSharedMemorySize, GEMM_SMEM);
    cudaFuncSetAttribute(mma_gemm_proj, cudaFuncAttributeMaxDynamicSharedMemorySize, GEMM_SMEM);

    // weight prep
    k_cvt<<<(CC * CC + 255) / 256, 256>>>(wq, wqd, CC * CC);
    k_cvt<<<(CC * CC + 255) / 256, 256>>>(wk, wkd, CC * CC);
    k_cvt<<<(CC * CC + 255) / 256, 256>>>(wv, wvd, CC * CC);
    k_tcvt<<<dim3(MLPH / 32, CC / 32), dim3(32, 8)>>>(w1, w1d, CC, MLPH);
    k_tcvt<<<dim3(CC / 32, MLPH / 32), dim3(32, 8)>>>(w2, w2d, MLPH, CC);

    // 1) LN stats + transpose-convert
    k_stats<<<dim3(NN_ / 32, BB), 256>>>(query, key, qe, ke);
    k_cvtT<<<dim3(NN_ / 32, CC / 32, BB), dim3(32, 8)>>>(query, key, qe, ke, gn, bn);

    // 2) projections (merged NT GEMMs, K=512) -> fp16
    {
        dim3 g(CC / 128, RR / 128, 3);
        mma_gemm_proj<<<g, 256, GEMM_SMEM>>>(
            Qa, Ka, Va, wqd, wkd, wvd,
            bq, bk, bv, Qpa, Kpa, Vpa);
    }

    // 3) attention + residual + LN2
    k_attn<<<RR, 256>>>(g2, b2);

    // 4) MLP1: H = gelu(L2 @ w1^T + b1)   Nd=2048, K=512
    {
        dim3 g(MLPH / 128, RR / 128);
        mma_gemm<1><<<g, 256, GEMM_SMEM>>>(L2a, w1d, b1, nullptr, Ha, MLPH, CC);
    }
    // 5) H2 = H @ w2^T + b2b              Nd=512, K=2048
    {
        dim3 g(CC / 128, RR / 128);
        mma_gemm<0><<<g, 256, GEMM_SMEM>>>(Ha, w2d, b2b, H2, nullptr, CC, MLPH);
    }

    // 6) out = transpose(X + H2)
    {
        dim3 g(NN_ / 32, CC / 32, BB);
        dim3 blk(32, 8);
        k_out<<<g, blk>>>(out);
    }
}

// round 12
// speedup vs baseline: 1.8177x; 1.8177x over previous
#include <cuda_runtime.h>
#include <cuda_bf16.h>
#include <cuda_fp16.h>
#include <math.h>
#include <stdint.h>

// Problem constants (fixed shapes)
#define BB   8
#define CC   512
#define NN_  2048
#define RR   (BB * NN_)      // 16384 positions
#define MLPH 2048
#define KH   9
#define PAD  4

// ---------------- scratch (device globals; no allocs allowed) ----------------
__device__ __align__(16) float g_Qt [(size_t)RR * CC];   // raw query (residual)
__device__ __align__(16) float g_X  [(size_t)RR * CC];
__device__ __align__(16) float g_H2 [(size_t)RR * CC];
__device__ __align__(16) float4 g_stats[RR];             // qm,qrs,km,krs

// fp16 activations
__device__ __align__(16) __half g_Qa [(size_t)RR * CC];
__device__ __align__(16) __half g_Ka [(size_t)RR * CC];
__device__ __align__(16) __half g_Va [(size_t)RR * CC];
__device__ __align__(16) __half g_Qpa[(size_t)RR * CC];
__device__ __align__(16) __half g_Kpa[(size_t)RR * CC];
__device__ __align__(16) __half g_Vpa[(size_t)RR * CC];
__device__ __align__(16) __half g_L2a[(size_t)RR * CC];
__device__ __align__(16) __half g_Ha [(size_t)RR * MLPH];

// fp16 weights
__device__ __align__(16) __half g_wq[CC * CC];
__device__ __align__(16) __half g_wk[CC * CC];
__device__ __align__(16) __half g_wv[CC * CC];
__device__ __align__(16) __half g_w1[MLPH * CC];  // w1^T
__device__ __align__(16) __half g_w2[CC * MLPH];  // w2^T

// ---------------- helpers ----------------------------------------------------
__device__ __forceinline__ uint32_t smem_u32(const void* p) {
    uint32_t a;
    asm("{ .reg .u64 t; cvta.to.shared.u64 t, %1; cvt.u32.u64 %0, t; }"
        : "=r"(a) : "l"(p));
    return a;
}
__device__ __forceinline__ void cpa16(uint32_t dst, const void* src) {
    asm volatile("cp.async.cg.shared.global [%0], [%1], 16;"
                 :: "r"(dst), "l"(src) : "memory");
}
#define CP_COMMIT() asm volatile("cp.async.commit_group;" ::: "memory")
#define CP_WAIT(n)  asm volatile("cp.async.wait_group %0;" :: "n"(n) : "memory")

__device__ __forceinline__ void ldsm4(uint32_t& r0, uint32_t& r1,
                                      uint32_t& r2, uint32_t& r3, uint32_t a) {
    asm volatile("ldmatrix.sync.aligned.m8n8.x4.shared.b16 {%0,%1,%2,%3}, [%4];"
                 : "=r"(r0), "=r"(r1), "=r"(r2), "=r"(r3) : "r"(a));
}
__device__ __forceinline__ void mma16816(float* c, uint32_t a0, uint32_t a1,
                                         uint32_t a2, uint32_t a3,
                                         uint32_t b0, uint32_t b1) {
    asm volatile(
        "mma.sync.aligned.m16n8k16.row.col.f32.f16.f16.f32 "
        "{%0,%1,%2,%3}, {%4,%5,%6,%7}, {%8,%9}, {%0,%1,%2,%3};"
        : "+f"(c[0]), "+f"(c[1]), "+f"(c[2]), "+f"(c[3])
        : "r"(a0), "r"(a1), "r"(a2), "r"(a3), "r"(b0), "r"(b1));
}
// smem tile rows of 64 fp16 (128B = 8 x 16B units); unit XOR-swizzled by row&7
__device__ __forceinline__ uint32_t swoff(int row, int kb) {
    return (uint32_t)((row << 7) + ((((kb >> 4) ^ (row & 7))) << 4));
}

// ============================================================================
// K1a: per-position LN stats (coalesced along n)
// ============================================================================
__global__ __launch_bounds__(256) void k_stats(
    const float* __restrict__ q,  const float* __restrict__ k,
    const float* __restrict__ qe, const float* __restrict__ ke)
{
    int b  = blockIdx.y;
    int n0 = blockIdx.x * 32;
    int tx = threadIdx.x & 31;
    int ty = threadIdx.x >> 5;     // 0..7
    size_t base = (size_t)b * CC * NN_ + n0 + tx;

    float qs = 0.f, qss = 0.f, ks = 0.f, kss = 0.f;
    for (int c = ty; c < CC; c += 8) {
        size_t idx = base + (size_t)c * NN_;
        float qv = q[idx] + qe[idx];
        float kv = k[idx] + ke[idx];
        qs += qv; qss += qv * qv;
        ks += kv; kss += kv * kv;
    }
    __shared__ float sm[4][8][32];
    sm[0][ty][tx] = qs; sm[1][ty][tx] = qss;
    sm[2][ty][tx] = ks; sm[3][ty][tx] = kss;
    __syncthreads();
    if (ty == 0) {
        float a0 = 0.f, a1 = 0.f, a2 = 0.f, a3 = 0.f;
#pragma unroll
        for (int w = 0; w < 8; w++) {
            a0 += sm[0][w][tx]; a1 += sm[1][w][tx];
            a2 += sm[2][w][tx]; a3 += sm[3][w][tx];
        }
        const float invC = 1.0f / CC;
        float qm = a0 * invC, km = a2 * invC;
        float qrs = rsqrtf(a1 * invC - qm * qm + 1e-5f);
        float krs = rsqrtf(a3 * invC - km * km + 1e-5f);
        g_stats[b * NN_ + n0 + tx] = make_float4(qm, qrs, km, krs);
    }
}

// ============================================================================
// K1b: transpose-convert: apply LN, emit pos-major fp16 (+ raw q fp32)
// ============================================================================
__global__ __launch_bounds__(256) void k_cvtT(
    const float* __restrict__ q,  const float* __restrict__ k,
    const float* __restrict__ qe, const float* __restrict__ ke,
    const float* __restrict__ gn, const float* __restrict__ bn)
{
    __shared__ float tQE[32][33], tKE[32][33], tQ[32][33], tK[32][33];
    int b  = blockIdx.z;
    int c0 = blockIdx.y * 32;
    int n0 = blockIdx.x * 32;
    int tx = threadIdx.x;      // 0..31
    int ty = threadIdx.y;      // 0..7

#pragma unroll
    for (int i = 0; i < 4; i++) {
        int cl = ty + i * 8;
        size_t idx = (size_t)b * CC * NN_ + (size_t)(c0 + cl) * NN_ + n0 + tx;
        float qv = q[idx], kv = k[idx];
        tQ [cl][tx] = qv;
        tK [cl][tx] = kv;
        tQE[cl][tx] = qv + qe[idx];
        tKE[cl][tx] = kv + ke[idx];
    }
    __syncthreads();

    int c = c0 + tx;
    float g = gn[c], bb = bn[c];
#pragma unroll
    for (int i = 0; i < 4; i++) {
        int nl = ty + i * 8;
        int r  = b * NN_ + n0 + nl;
        float4 s = g_stats[r];
        float qo = (tQE[tx][nl] - s.x) * s.y * g + bb;
        float ko = (tKE[tx][nl] - s.z) * s.w * g + bb;
        size_t o = (size_t)r * CC + c;
        g_Qa[o] = __float2half_rn(qo);
        g_Ka[o] = __float2half_rn(ko);
        g_Va[o] = __float2half_rn(tK[tx][nl]);
        g_Qt[o] = tQ[tx][nl];
    }
}

// ============================================================================
// plain fp16 mma.sync GEMM:  C[M,Nd] = A[M,K] * B[Nd,K]^T (+bias)
// 128x128x64 CTA tile, 8 warps (2x4), 3-stage cp.async, 2 CTAs/SM.
// OUT=0: fp32 store.  OUT=1: exact-GELU fp16 store.  OUT=2: fp16 store.
// ============================================================================
#define ST_BYTES 32768          // per stage: A 16K | B 16K   (128x64 halfs each)
#define NSTAGE   3
#define GEMM_SMEM (NSTAGE * ST_BYTES)

__device__ __forceinline__ void ld_tile(uint32_t sdst,
                                        const __half* __restrict__ src,
                                        int ldk) {
    int tid = threadIdx.x;
#pragma unroll
    for (int it = 0; it < 4; it++) {
        int f   = tid + it * 256;   // 0..1023
        int row = f >> 3;           // 0..127
        int u   = f & 7;            // 16B unit within 128B row
        uint32_t d = sdst + (uint32_t)(row << 7) + (uint32_t)(((u ^ (row & 7))) << 4);
        cpa16(d, src + (size_t)row * ldk + u * 8);
    }
}

__device__ __forceinline__ void ld_stage(
    uint32_t sbase,
    const __half* __restrict__ A, const __half* __restrict__ B,
    int brow, int bcol, int K, int k0)
{
    ld_tile(sbase +     0, A + (size_t)brow * K + k0, K);
    ld_tile(sbase + 16384, B + (size_t)bcol * K + k0, K);
}

template <int OUT>
__device__ __forceinline__ void gemm_body(
    const __half* __restrict__ A, const __half* __restrict__ B,
    const float* __restrict__ bias,
    float* __restrict__ Cf, __half* __restrict__ Ch,
    int Nd, int K, int brow, int bcol, char* smem)
{
    uint32_t sb = smem_u32(smem);
    const int tid  = threadIdx.x;
    const int lane = tid & 31;
    const int wid  = tid >> 5;
    const int wr   = wid >> 2;          // 0..1 (64 m rows)
    const int wc   = wid & 3;           // 0..3 (32 n cols)

    float acc[4][4][4];
#pragma unroll
    for (int i = 0; i < 4; i++)
#pragma unroll
        for (int j = 0; j < 4; j++)
#pragma unroll
            for (int x = 0; x < 4; x++) acc[i][j][x] = 0.f;

    const int a_row = wr * 64 + (lane & 15);
    const int a_kb  = (lane & 16);
    const int b_row = wc * 32 + (lane & 7) + ((lane & 16) ? 8 : 0);
    const int b_kb  = ((lane & 8) ? 16 : 0);

    const int NCH = K >> 6;   // 64-k chunks

    // prologue: stages 0 and 1 in flight
    ld_stage(sb, A, B, brow, bcol, K, 0);
    CP_COMMIT();
    ld_stage(sb + ST_BYTES, A, B, brow, bcol, K, 64);
    CP_COMMIT();

    int s = 0;
    for (int ch = 0; ch < NCH; ch++) {
        if (ch + 2 < NCH) {
            int sn = s + 2; if (sn >= NSTAGE) sn -= NSTAGE;
            ld_stage(sb + (uint32_t)(sn * ST_BYTES), A, B,
                     brow, bcol, K, (ch + 2) << 6);
            CP_COMMIT();
            CP_WAIT(2);
        } else if (ch + 1 < NCH) {
            CP_WAIT(1);
        } else {
            CP_WAIT(0);
        }
        __syncthreads();

        uint32_t sa = sb + (uint32_t)(s * ST_BYTES);
#pragma unroll
        for (int ks = 0; ks < 4; ks++) {
            int kso = ks * 32;          // bytes: 16 k per step
            uint32_t bmat[4][2];
#pragma unroll
            for (int jp = 0; jp < 2; jp++) {
                uint32_t addr = sa + 16384 + swoff(b_row + jp * 16, b_kb + kso);
                ldsm4(bmat[2*jp][0], bmat[2*jp][1],
                      bmat[2*jp+1][0], bmat[2*jp+1][1], addr);
            }
#pragma unroll
            for (int i = 0; i < 4; i++) {
                uint32_t a0, a1, a2, a3;
                ldsm4(a0, a1, a2, a3, sa + swoff(a_row + i * 16, a_kb + kso));
#pragma unroll
                for (int j = 0; j < 4; j++)
                    mma16816(acc[i][j], a0, a1, a2, a3, bmat[j][0], bmat[j][1]);
            }
        }
        __syncthreads();
        s++; if (s >= NSTAGE) s = 0;
    }

    const int grp = lane >> 2, qr = lane & 3;
#pragma unroll
    for (int i = 0; i < 4; i++) {
        int r0 = brow + wr * 64 + i * 16 + grp;
#pragma unroll
        for (int j = 0; j < 4; j++) {
            int col = bcol + wc * 32 + j * 8 + qr * 2;
            float b0 = bias[col], b1 = bias[col + 1];
            float v00 = acc[i][j][0] + b0, v01 = acc[i][j][1] + b1;
            float v10 = acc[i][j][2] + b0, v11 = acc[i][j][3] + b1;
            if (OUT == 0) {
                *(float2*)(Cf + (size_t)r0 * Nd + col)       = make_float2(v00, v01);
                *(float2*)(Cf + (size_t)(r0 + 8) * Nd + col) = make_float2(v10, v11);
            } else if (OUT == 1) {
                v00 = 0.5f * v00 * (1.0f + erff(v00 * 0.70710678118654752f));
                v01 = 0.5f * v01 * (1.0f + erff(v01 * 0.70710678118654752f));
                v10 = 0.5f * v10 * (1.0f + erff(v10 * 0.70710678118654752f));
                v11 = 0.5f * v11 * (1.0f + erff(v11 * 0.70710678118654752f));
                *(__half2*)(Ch + (size_t)r0 * Nd + col)       = __floats2half2_rn(v00, v01);
                *(__half2*)(Ch + (size_t)(r0 + 8) * Nd + col) = __floats2half2_rn(v10, v11);
            } else {
                *(__half2*)(Ch + (size_t)r0 * Nd + col)       = __floats2half2_rn(v00, v01);
                *(__half2*)(Ch + (size_t)(r0 + 8) * Nd + col) = __floats2half2_rn(v10, v11);
            }
        }
    }
}

template <int OUT>
__global__ __launch_bounds__(256, 2) void mma_gemm(
    const __half* __restrict__ A, const __half* __restrict__ B,
    const float* __restrict__ bias,
    float* __restrict__ Cf, __half* __restrict__ Ch,
    int Nd, int K)
{
    extern __shared__ char smem[];
    gemm_body<OUT>(A, B, bias, Cf, Ch,
                   Nd, K, blockIdx.y * 128, blockIdx.x * 128, smem);
}

// merged projection GEMM: blockIdx.z selects (Q,K,V); fp16 outputs
__global__ __launch_bounds__(256, 2) void mma_gemm_proj(
    const __half* __restrict__ A0, const __half* __restrict__ A1,
    const __half* __restrict__ A2,
    const __half* __restrict__ B0, const __half* __restrict__ B1,
    const __half* __restrict__ B2,
    const float* __restrict__ b0, const float* __restrict__ b1,
    const float* __restrict__ b2,
    __half* __restrict__ C0, __half* __restrict__ C1, __half* __restrict__ C2)
{
    extern __shared__ char smem[];
    int z = blockIdx.z;
    const __half* Aa = (z == 0) ? A0 : (z == 1) ? A1 : A2;
    const __half* Bb = (z == 0) ? B0 : (z == 1) ? B1 : B2;
    const float* bs = (z == 0) ? b0 : (z == 1) ? b1 : b2;
    __half* Cc = (z == 0) ? C0 : (z == 1) ? C1 : C2;
    gemm_body<2>(Aa, Bb, bs, nullptr, Cc,
                 CC, CC, blockIdx.y * 128, blockIdx.x * 128, smem);
}

// ============================================================================
// K4: warp-per-position windowed attention + residual + LN2.
// No smem, no __syncthreads; all reductions are warp butterflies.
// Lane owns 16 channels: {8l..8l+7} and {256+8l..256+8l+7}.
// ============================================================================
__global__ __launch_bounds__(256) void k_attn(
    const float* __restrict__ g2, const float* __restrict__ b2)
{
    int r    = blockIdx.x * 8 + (threadIdx.x >> 5);   // position index
    int lane = threadIdx.x & 31;
    int bb = r >> 11;
    int n  = r & (NN_ - 1);
    const float scale = 0.044194173824159216f;  // 512^-0.5

    size_t qb = (size_t)r * CC;
    int cA = 8 * lane;          // first channel block
    int cB = 256 + 8 * lane;    // second channel block

    // load Q (16 halfs)
    __half2 qh[8];
    *(uint4*)&qh[0] = *(const uint4*)(g_Qpa + qb + cA);
    *(uint4*)&qh[4] = *(const uint4*)(g_Qpa + qb + cB);
    float qf[16];
#pragma unroll
    for (int i = 0; i < 8; i++) {
        float2 f = __half22float2(qh[i]);
        qf[2*i] = f.x; qf[2*i+1] = f.y;
    }

    bool   valid[KH];
    size_t nb[KH];
#pragma unroll
    for (int j = 0; j < KH; j++) {
        int nn = n + j - PAD;
        valid[j] = (nn >= 0) && (nn < NN_);
        nb[j] = valid[j] ? ((size_t)(bb * NN_ + nn)) * CC : 0;
    }

    float acc[KH];
#pragma unroll
    for (int j = 0; j < KH; j++) {
        float s = 0.f;
        if (valid[j]) {
            __half2 kh[8];
            *(uint4*)&kh[0] = *(const uint4*)(g_Kpa + nb[j] + cA);
            *(uint4*)&kh[4] = *(const uint4*)(g_Kpa + nb[j] + cB);
#pragma unroll
            for (int i = 0; i < 8; i++) {
                float2 f = __half22float2(kh[i]);
                s = fmaf(qf[2*i], f.x, s);
                s = fmaf(qf[2*i+1], f.y, s);
            }
        }
        acc[j] = s;
    }
    // warp allreduce (butterfly) for each logit
#pragma unroll
    for (int j = 0; j < KH; j++) {
#pragma unroll
        for (int o = 16; o > 0; o >>= 1)
            acc[j] += __shfl_xor_sync(0xffffffffu, acc[j], o);
    }

    // softmax (all lanes redundantly)
    float m = acc[0];
#pragma unroll
    for (int j = 1; j < KH; j++) m = fmaxf(m, acc[j]);
    float wj[KH], es = 0.f;
#pragma unroll
    for (int j = 0; j < KH; j++) { wj[j] = expf(acc[j] - m); es += wj[j]; }
    float inv = scale / es;
#pragma unroll
    for (int j = 0; j < KH; j++) wj[j] *= inv;

    // V aggregation
    float attn[16];
#pragma unroll
    for (int i = 0; i < 16; i++) attn[i] = 0.f;
#pragma unroll
    for (int j = 0; j < KH; j++) {
        if (valid[j]) {
            __half2 vh[8];
            *(uint4*)&vh[0] = *(const uint4*)(g_Vpa + nb[j] + cA);
            *(uint4*)&vh[4] = *(const uint4*)(g_Vpa + nb[j] + cB);
            float w = wj[j];
#pragma unroll
            for (int i = 0; i < 8; i++) {
                float2 f = __half22float2(vh[i]);
                attn[2*i]   = fmaf(w, f.x, attn[2*i]);
                attn[2*i+1] = fmaf(w, f.y, attn[2*i+1]);
            }
        }
    }

    // residual + LN2 stats
    float x[16];
    {
        float4 t0 = *(const float4*)(g_Qt + qb + cA);
        float4 t1 = *(const float4*)(g_Qt + qb + cA + 4);
        float4 t2 = *(const float4*)(g_Qt + qb + cB);
        float4 t3 = *(const float4*)(g_Qt + qb + cB + 4);
        x[0]=t0.x+attn[0];  x[1]=t0.y+attn[1];  x[2]=t0.z+attn[2];  x[3]=t0.w+attn[3];
        x[4]=t1.x+attn[4];  x[5]=t1.y+attn[5];  x[6]=t1.z+attn[6];  x[7]=t1.w+attn[7];
        x[8]=t2.x+attn[8];  x[9]=t2.y+attn[9];  x[10]=t2.z+attn[10]; x[11]=t2.w+attn[11];
        x[12]=t3.x+attn[12]; x[13]=t3.y+attn[13]; x[14]=t3.z+attn[14]; x[15]=t3.w+attn[15];
    }
    // store X
    *(float4*)(g_X + qb + cA)     = make_float4(x[0], x[1], x[2], x[3]);
    *(float4*)(g_X + qb + cA + 4) = make_float4(x[4], x[5], x[6], x[7]);
    *(float4*)(g_X + qb + cB)     = make_float4(x[8], x[9], x[10], x[11]);
    *(float4*)(g_X + qb + cB + 4) = make_float4(x[12], x[13], x[14], x[15]);

    float xs = 0.f, xss = 0.f;
#pragma unroll
    for (int i = 0; i < 16; i++) { xs += x[i]; xss += x[i] * x[i]; }
#pragma unroll
    for (int o = 16; o > 0; o >>= 1) {
        xs  += __shfl_xor_sync(0xffffffffu, xs,  o);
        xss += __shfl_xor_sync(0xffffffffu, xss, o);
    }
    const float invC = 1.0f / CC;
    float mean = xs * invC;
    float rstd = rsqrtf(xss * invC - mean * mean + 1e-5f);

    // LN2 + fp16 store
    float4 gA0 = *(const float4*)(g2 + cA);
    float4 gA1 = *(const float4*)(g2 + cA + 4);
    float4 gB0 = *(const float4*)(g2 + cB);
    float4 gB1 = *(const float4*)(g2 + cB + 4);
    float4 bA0 = *(const float4*)(b2 + cA);
    float4 bA1 = *(const float4*)(b2 + cA + 4);
    float4 bB0 = *(const float4*)(b2 + cB);
    float4 bB1 = *(const float4*)(b2 + cB + 4);
    float gg[16] = {gA0.x,gA0.y,gA0.z,gA0.w, gA1.x,gA1.y,gA1.z,gA1.w,
                    gB0.x,gB0.y,gB0.z,gB0.w, gB1.x,gB1.y,gB1.z,gB1.w};
    float bbv[16] = {bA0.x,bA0.y,bA0.z,bA0.w, bA1.x,bA1.y,bA1.z,bA1.w,
                     bB0.x,bB0.y,bB0.z,bB0.w, bB1.x,bB1.y,bB1.z,bB1.w};
    __half2 oh[8];
#pragma unroll
    for (int i = 0; i < 8; i++) {
        float v0 = (x[2*i]   - mean) * rstd * gg[2*i]   + bbv[2*i];
        float v1 = (x[2*i+1] - mean) * rstd * gg[2*i+1] + bbv[2*i+1];
        oh[i] = __floats2half2_rn(v0, v1);
    }
    *(uint4*)(g_L2a + qb + cA) = *(uint4*)&oh[0];
    *(uint4*)(g_L2a + qb + cB) = *(uint4*)&oh[4];
}

// ============================================================================
// weight prep
// ============================================================================
__global__ __launch_bounds__(256) void k_cvt(
    const float* __restrict__ src, __half* __restrict__ dst, int n)
{
    int i = blockIdx.x * 256 + threadIdx.x;
    if (i < n) dst[i] = __float2half_rn(src[i]);
}

// src [R, Cc] fp32 -> dst [Cc, R] fp16
__global__ void k_tcvt(const float* __restrict__ src,
                       __half* __restrict__ dst, int R, int Cc)
{
    __shared__ float t[32][33];
    int c0 = blockIdx.x * 32, r0 = blockIdx.y * 32;
    int tx = threadIdx.x, ty = threadIdx.y;
#pragma unroll
    for (int i = 0; i < 4; i++)
        t[ty + i * 8][tx] = src[(size_t)(r0 + ty + i * 8) * Cc + c0 + tx];
    __syncthreads();
#pragma unroll
    for (int i = 0; i < 4; i++) {
        float v = t[tx][ty + i * 8];
        dst[(size_t)(c0 + ty + i * 8) * R + r0 + tx] = __float2half_rn(v);
    }
}

// ============================================================================
// K7: out[b,c,n] = X[r,c] + H2[r,c]
// ============================================================================
__global__ __launch_bounds__(256) void k_out(float* __restrict__ out)
{
    __shared__ float t[32][33];
    int bb = blockIdx.z;
    int c0 = blockIdx.y * 32;
    int n0 = blockIdx.x * 32;
    int tx = threadIdx.x;
    int ty = threadIdx.y;
#pragma unroll
    for (int i = 0; i < 4; i++) {
        int n = n0 + ty + i * 8;
        size_t idx = ((size_t)(bb * NN_ + n)) * CC + c0 + tx;
        t[tx][ty + i * 8] = g_X[idx] + g_H2[idx];
    }
    __syncthreads();
#pragma unroll
    for (int i = 0; i < 4; i++) {
        int c = c0 + ty + i * 8;
        out[(size_t)bb * CC * NN_ + (size_t)c * NN_ + n0 + tx] = t[ty + i * 8][tx];
    }
}

// ============================================================================
extern "C" void kernel_launch(void* const* d_in, const int* in_sizes, int n_in,
                              void* d_out, int out_size)
{
    const float* query = (const float*)d_in[0];
    const float* key   = (const float*)d_in[1];
    const float* qe    = (const float*)d_in[2];
    const float* ke    = (const float*)d_in[3];
    const float* wq    = (const float*)d_in[4];
    const float* bq    = (const float*)d_in[5];
    const float* wk    = (const float*)d_in[6];
    const float* bk    = (const float*)d_in[7];
    const float* wv    = (const float*)d_in[8];
    const float* bv    = (const float*)d_in[9];
    const float* gn    = (const float*)d_in[10];
    const float* bn    = (const float*)d_in[11];
    const float* g2    = (const float*)d_in[12];
    const float* b2    = (const float*)d_in[13];
    const float* w1    = (const float*)d_in[14];
    const float* b1    = (const float*)d_in[15];
    const float* w2    = (const float*)d_in[16];
    const float* b2b   = (const float*)d_in[17];
    float* out = (float*)d_out;

    float* H2;
    __half *Qa, *Ka, *Va, *Qpa, *Kpa, *Vpa, *L2a, *Ha;
    __half *wqd, *wkd, *wvd, *w1d, *w2d;
    cudaGetSymbolAddress((void**)&H2,  g_H2);
    cudaGetSymbolAddress((void**)&Qa,  g_Qa);
    cudaGetSymbolAddress((void**)&Ka,  g_Ka);
    cudaGetSymbolAddress((void**)&Va,  g_Va);
    cudaGetSymbolAddress((void**)&Qpa, g_Qpa);
    cudaGetSymbolAddress((void**)&Kpa, g_Kpa);
    cudaGetSymbolAddress((void**)&Vpa, g_Vpa);
    cudaGetSymbolAddress((void**)&L2a, g_L2a);
    cudaGetSymbolAddress((void**)&Ha,  g_Ha);
    cudaGetSymbolAddress((void**)&wqd, g_wq);
    cudaGetSymbolAddress((void**)&wkd, g_wk);
    cudaGetSymbolAddress((void**)&wvd, g_wv);
    cudaGetSymbolAddress((void**)&w1d, g_w1);
    cudaGetSymbolAddress((void**)&w2d, g_w2);

    cudaFuncSetAttribute(mma_gemm<0>,  cudaFuncAttributeMaxDynamicSharedMemorySize, GEMM_SMEM);
    cudaFuncSetAttribute(mma_gemm<1>,  cudaFuncAttributeMaxDynamicSharedMemorySize, GEMM_SMEM);
    cudaFuncSetAttribute(mma_gemm_proj, cudaFuncAttributeMaxDynamicSharedMemorySize, GEMM_SMEM);

    // weight prep
    k_cvt<<<(CC * CC + 255) / 256, 256>>>(wq, wqd, CC * CC);
    k_cvt<<<(CC * CC + 255) / 256, 256>>>(wk, wkd, CC * CC);
    k_cvt<<<(CC * CC + 255) / 256, 256>>>(wv, wvd, CC * CC);
    k_tcvt<<<dim3(MLPH / 32, CC / 32), dim3(32, 8)>>>(w1, w1d, CC, MLPH);
    k_tcvt<<<dim3(CC / 32, MLPH / 32), dim3(32, 8)>>>(w2, w2d, MLPH, CC);

    // 1) LN stats + transpose-convert
    k_stats<<<dim3(NN_ / 32, BB), 256>>>(query, key, qe, ke);
    k_cvtT<<<dim3(NN_ / 32, CC / 32, BB), dim3(32, 8)>>>(query, key, qe, ke, gn, bn);

    // 2) projections (merged NT GEMMs, K=512) -> fp16
    {
        dim3 g(CC / 128, RR / 128, 3);
        mma_gemm_proj<<<g, 256, GEMM_SMEM>>>(
            Qa, Ka, Va, wqd, wkd, wvd,
            bq, bk, bv, Qpa, Kpa, Vpa);
    }

    // 3) attention + residual + LN2 (warp per position)
    k_attn<<<RR / 8, 256>>>(g2, b2);

    // 4) MLP1: H = gelu(L2 @ w1^T + b1)   Nd=2048, K=512
    {
        dim3 g(MLPH / 128, RR / 128);
        mma_gemm<1><<<g, 256, GEMM_SMEM>>>(L2a, w1d, b1, nullptr, Ha, MLPH, CC);
    }
    // 5) H2 = H @ w2^T + b2b              Nd=512, K=2048
    {
        dim3 g(CC / 128, RR / 128);
        mma_gemm<0><<<g, 256, GEMM_SMEM>>>(Ha, w2d, b2b, H2, nullptr, CC, MLPH);
    }

    // 6) out = transpose(X + H2)
    {
        dim3 g(NN_ / 32, CC / 32, BB);
        dim3 blk(32, 8);
        k_out<<<g, blk>>>(out);
    }
}